// round 11
// baseline (speedup 1.0000x reference)
#include <cuda_runtime.h>
#include <cuda_fp16.h>
#include <cstdint>

#define N_ROWS 8192
#define D      256
#define K      8192
#define DEPTH  4
#define CB_STRIDE ((K + 1) * D)
#define LOSS_SCALE (0.25f / (4.0f * 2097152.0f))
#define MARGIN 1.5e-2f
#define FLT_BIG 3.402823466e38f

#define BM 128
#define BN2 256
#define ATILE 16384                 // 128 rows x 128B
#define BTILE 32768                 // 256 rows x 128B
#define STG (ATILE + BTILE)         // 49152
#define SMEMT (2 * STG)             // 98304 -> 2 CTAs/SM

// ---------------- persistent scratch ----------------
__device__ __align__(256) float  g_res[N_ROWS * D];
__device__ __align__(256) float  g_agg[N_ROWS * D];
__device__ __align__(256) __half g_res_h[N_ROWS * D];
__device__ __align__(256) __half g_cb_h[DEPTH * K * D];
__device__ __align__(16)  float  g_cc[DEPTH * K];
__device__ __align__(16)  unsigned long long g_top[N_ROWS * 64];   // 32 tiles x top-2

// ---------------- helpers ----------------
__device__ __forceinline__ uint32_t smem_u32(const void* p) {
    uint32_t a;
    asm("{ .reg .u64 t; cvta.to.shared.u64 t, %1; cvt.u32.u64 %0, t; }" : "=r"(a) : "l"(p));
    return a;
}
__device__ __forceinline__ uint32_t swz(uint32_t x) { return x ^ ((x >> 3) & 0x70u); }
__device__ __forceinline__ uint32_t h2_as_u32(__half2 h) {
    return *reinterpret_cast<uint32_t*>(&h);
}
__device__ __forceinline__ unsigned int f2ord(float f) {
    unsigned int u = __float_as_uint(f);
    return (u & 0x80000000u) ? ~u : (u | 0x80000000u);
}
__device__ __forceinline__ float ord2f(unsigned int o) {
    unsigned int u = (o & 0x80000000u) ? (o & 0x7FFFFFFFu) : ~o;
    return __uint_as_float(u);
}
__device__ __forceinline__ void merge2(unsigned long long& b1, unsigned long long& b2,
                                       unsigned long long o1, unsigned long long o2) {
    if (o1 < b1) { b2 = (b1 < o2) ? b1 : o2; b1 = o1; }
    else if (o1 < b2) { b2 = o1; }
}
__device__ __forceinline__ void push2(unsigned long long& b1, unsigned long long& b2,
                                      unsigned long long k) {
    if (k < b1) { b2 = b1; b1 = k; }
    else if (k < b2) { b2 = k; }
}

__device__ __forceinline__ void cpa16(uint32_t dst, const void* src) {
    asm volatile("cp.async.cg.shared.global [%0], [%1], 16;" :: "r"(dst), "l"(src));
}
#define CP_COMMIT() asm volatile("cp.async.commit_group;" ::: "memory")
#define CP_WAIT(n)  asm volatile("cp.async.wait_group %0;" :: "n"(n) : "memory")

#define LDSM4(r0, r1, r2, r3, a) \
    asm volatile("ldmatrix.sync.aligned.m8n8.x4.shared.b16 {%0,%1,%2,%3}, [%4];" \
                 : "=r"(r0), "=r"(r1), "=r"(r2), "=r"(r3) : "r"(a))

// f16-accumulator HMMA: D,C are 2 regs (4 halves)
#define MMA16816H(c0, c1, a, b0, b1) \
    asm volatile("mma.sync.aligned.m16n8k16.row.col.f16.f16.f16.f16 " \
                 "{%0,%1},{%2,%3,%4,%5},{%6,%7},{%0,%1};" \
                 : "+r"(c0), "+r"(c1) \
                 : "r"((a)[0]), "r"((a)[1]), "r"((a)[2]), "r"((a)[3]), "r"(b0), "r"(b1))

// reduce two values across a 256-thread block; result in thread 0
__device__ __forceinline__ void blockReduce2_256(float& a, float& b) {
    __shared__ float sa[8], sb2[8];
    int lane = threadIdx.x & 31, w = threadIdx.x >> 5;
#pragma unroll
    for (int o = 16; o > 0; o >>= 1) {
        a += __shfl_down_sync(0xffffffffu, a, o);
        b += __shfl_down_sync(0xffffffffu, b, o);
    }
    if (lane == 0) { sa[w] = a; sb2[w] = b; }
    __syncthreads();
    if (w == 0) {
        a = (lane < 8) ? sa[lane] : 0.f;
        b = (lane < 8) ? sb2[lane] : 0.f;
#pragma unroll
        for (int o = 4; o > 0; o >>= 1) {
            a += __shfl_down_sync(0xffu, a, o);
            b += __shfl_down_sync(0xffu, b, o);
        }
    }
}

// ---------------- setup ----------------
__global__ void k_init(const float* __restrict__ x) {
    int i = blockIdx.x * blockDim.x + threadIdx.x;
    if (i < N_ROWS * D) {
        float v = x[i];
        g_res[i] = v; g_agg[i] = 0.f;
        g_res_h[i] = __float2half_rn(v);
    }
}

__global__ void k_cb(const float* __restrict__ cbs) {
    int rid = blockIdx.x;                     // 0 .. DEPTH*K-1
    int dd = rid / K, r = rid % K;
    float v = cbs[(size_t)dd * CB_STRIDE + (size_t)r * D + threadIdx.x];
    g_cb_h[(size_t)rid * D + threadIdx.x] = __float2half_rn(v);
    float a = v * v, b = 0.f;
    blockReduce2_256(a, b);
    if (threadIdx.x == 0) g_cc[rid] = a;
}

__global__ void k_zero(float* __restrict__ loss) {
    if (threadIdx.x == 0) *loss = 0.f;
}

// ---------------- HMMA GEMM (f16 acc, 64x64 warp tiles) + per-CTA top-2 ----
// grid = (64, 32), block = 256 (8 warps: 2 row x 4 col)
// CTA tile 128 rows x 256 cands, K-loop of 4 chunk iterations, 2-stage pipe.
__global__ void __launch_bounds__(256, 2) k_gemm(int dep) {
    extern __shared__ char smem[];
    const uint32_t sb = smem_u32(smem);
    const int tid = threadIdx.x, lane = tid & 31, wid = tid >> 5;
    const int wm = wid & 1, wn = wid >> 1;         // warp tile: 64 rows x 64 cols
    const int rowBase = blockIdx.x * BM, candBase = blockIdx.y * BN2;

    const char* Ag = (const char*)(g_res_h + (size_t)rowBase * D);
    const char* Bg = (const char*)(g_cb_h + ((size_t)dep * K + (size_t)candBase) * D);

    const int r0 = tid >> 3, j0 = tid & 7;
    uint32_t sdst[8];
#pragma unroll
    for (int i = 0; i < 8; i++) sdst[i] = swz((uint32_t)(r0 + i * 32) * 128u + j0 * 16u);
    const uint32_t gA = (uint32_t)r0 * 512u + (uint32_t)j0 * 16u;

    uint32_t acc[4][8][2];
#pragma unroll
    for (int a = 0; a < 4; a++)
#pragma unroll
        for (int b = 0; b < 8; b++) { acc[a][b][0] = 0u; acc[a][b][1] = 0u; }

    const uint32_t aLin = (uint32_t)((wm * 64 + (lane & 15)) * 128 + (lane >> 4) * 16);
    const uint32_t bLin = (uint32_t)((wn * 64 + (lane & 7) + ((lane >> 4) << 3)) * 128 +
                                     ((lane >> 3) & 1) * 16);

    // prologue: chunk 0 -> stage 0
#pragma unroll
    for (int i = 0; i < 4; i++) cpa16(sb + sdst[i], Ag + gA + i * 32u * 512u);
#pragma unroll
    for (int i = 0; i < 8; i++) cpa16(sb + ATILE + sdst[i], Bg + gA + i * 32u * 512u);
    CP_COMMIT();

#pragma unroll
    for (int kc = 0; kc < 4; kc++) {
        if (kc < 3) {
            const uint32_t stg = (uint32_t)((kc + 1) & 1) * STG;
            const uint32_t ko = (uint32_t)(kc + 1) * 128u;
#pragma unroll
            for (int i = 0; i < 4; i++)
                cpa16(sb + stg + sdst[i], Ag + gA + i * 32u * 512u + ko);
#pragma unroll
            for (int i = 0; i < 8; i++)
                cpa16(sb + stg + ATILE + sdst[i], Bg + gA + i * 32u * 512u + ko);
            CP_COMMIT();
            CP_WAIT(1);
        } else {
            CP_WAIT(0);
        }
        __syncthreads();     // cp.async visibility across threads

        const uint32_t aT = sb + (uint32_t)(kc & 1) * STG;
        const uint32_t bT = aT + ATILE;
#pragma unroll
        for (int ks = 0; ks < 4; ks++) {
            uint32_t Af[4][4], Bf[4][4];
#pragma unroll
            for (int ma = 0; ma < 4; ma++)
                LDSM4(Af[ma][0], Af[ma][1], Af[ma][2], Af[ma][3],
                      aT + swz(aLin + ma * 16 * 128 + ks * 32));
#pragma unroll
            for (int nb = 0; nb < 4; nb++)
                LDSM4(Bf[nb][0], Bf[nb][1], Bf[nb][2], Bf[nb][3],
                      bT + swz(bLin + nb * 16 * 128 + ks * 32));
#pragma unroll
            for (int ma = 0; ma < 4; ma++)
#pragma unroll
                for (int nb = 0; nb < 4; nb++) {
                    MMA16816H(acc[ma][nb * 2 + 0][0], acc[ma][nb * 2 + 0][1],
                              Af[ma], Bf[nb][0], Bf[nb][1]);
                    MMA16816H(acc[ma][nb * 2 + 1][0], acc[ma][nb * 2 + 1][1],
                              Af[ma], Bf[nb][2], Bf[nb][3]);
                }
        }
        __syncthreads();     // protect stage (kc&1) before it is overwritten
    }

    // ---- epilogue: per-row top-2 over this CTA's 256 cols ----
    unsigned long long* sTop = (unsigned long long*)smem;   // [128 rows][4 wn][2]
    const float* cc = g_cc + (size_t)dep * K;
    const int colBase = candBase + wn * 64 + (lane & 3) * 2;

    float2 ccv[8];
#pragma unroll
    for (int g = 0; g < 8; g++) ccv[g] = *(const float2*)&cc[colBase + g * 8];

#pragma unroll
    for (int ma = 0; ma < 4; ma++) {
        float d1[2] = {FLT_BIG, FLT_BIG}, d2[2] = {FLT_BIG, FLT_BIG};
        int i1[2] = {0, 0}, i2[2] = {0, 0};
#pragma unroll
        for (int g = 0; g < 8; g++) {
            const int col = colBase + g * 8;
#pragma unroll
            for (int rb = 0; rb < 2; rb++) {
                __half2 h = *reinterpret_cast<__half2*>(&acc[ma][g][rb]);
                float2 f = __half22float2(h);
                float k0 = fmaf(-2.f, f.x, ccv[g].x);
                float k1 = fmaf(-2.f, f.y, ccv[g].y);
                if (k0 < d2[rb]) {
                    if (k0 < d1[rb]) { d2[rb] = d1[rb]; i2[rb] = i1[rb]; d1[rb] = k0; i1[rb] = col; }
                    else { d2[rb] = k0; i2[rb] = col; }
                }
                if (k1 < d2[rb]) {
                    if (k1 < d1[rb]) { d2[rb] = d1[rb]; i2[rb] = i1[rb]; d1[rb] = k1; i1[rb] = col + 1; }
                    else { d2[rb] = k1; i2[rb] = col + 1; }
                }
            }
        }
#pragma unroll
        for (int rb = 0; rb < 2; rb++) {
            unsigned long long b1 =
                ((unsigned long long)f2ord(d1[rb]) << 32) | (unsigned int)i1[rb];
            unsigned long long b2 =
                ((unsigned long long)f2ord(d2[rb]) << 32) | (unsigned int)i2[rb];
#pragma unroll
            for (int off = 1; off <= 2; off <<= 1) {
                unsigned long long o1 = __shfl_xor_sync(0xffffffffu, b1, off);
                unsigned long long o2 = __shfl_xor_sync(0xffffffffu, b2, off);
                merge2(b1, b2, o1, o2);
            }
            if ((lane & 3) == 0) {
                int rl = wm * 64 + ma * 16 + rb * 8 + (lane >> 2);
                sTop[(rl * 4 + wn) * 2 + 0] = b1;
                sTop[(rl * 4 + wn) * 2 + 1] = b2;
            }
        }
    }
    __syncthreads();
    if (tid < 128) {
        unsigned long long p1 = sTop[tid * 8 + 0];
        unsigned long long p2 = sTop[tid * 8 + 1];
#pragma unroll
        for (int j = 1; j < 4; j++)
            merge2(p1, p2, sTop[tid * 8 + j * 2], sTop[tid * 8 + j * 2 + 1]);
        size_t go = (size_t)(rowBase + tid) * 64 + blockIdx.y * 2;
        g_top[go + 0] = p1;
        g_top[go + 1] = p2;
    }
}

// ---------------- fused select + rescore + update: warp per row ----------------
// grid = N_ROWS/8 = 1024, block = 256 (8 warps)
__global__ void __launch_bounds__(256) k_finish(
        const float* __restrict__ x, const float* __restrict__ cb,
        float* __restrict__ out, float* __restrict__ codes,
        float* __restrict__ loss, int dep) {
    const int w = threadIdx.x >> 5, lane = threadIdx.x & 31;
    const int row = blockIdx.x * 8 + w;
    __shared__ unsigned long long se[8][64];
    __shared__ int sql[8][64];
    __shared__ float wloss[8];

    const unsigned long long* gt = g_top + (size_t)row * 64;
    unsigned long long b1 = ~0ull, b2 = ~0ull;
#pragma unroll
    for (int i = 0; i < 2; i++) {
        unsigned long long e = gt[lane + i * 32];
        se[w][lane + i * 32] = e;
        push2(b1, b2, e);
    }
#pragma unroll
    for (int off = 16; off > 0; off >>= 1) {
        unsigned long long o1 = __shfl_xor_sync(0xffffffffu, b1, off);
        unsigned long long o2 = __shfl_xor_sync(0xffffffffu, b2, off);
        merge2(b1, b2, o1, o2);
    }
    float d1 = ord2f((unsigned int)(b1 >> 32));
    float d2 = ord2f((unsigned int)(b2 >> 32));
    int idx = (int)(b1 & 0xFFFFFFFFu);

    const float4* rr = (const float4*)(g_res + (size_t)row * D);
    float4 r0 = rr[lane * 2], r1 = rr[lane * 2 + 1];

    if (d2 - d1 < MARGIN) {
        const float thr = d1 + MARGIN;
        int nq = 0;
        __syncwarp();
#pragma unroll
        for (int i = 0; i < 2; i++) {
            unsigned long long e = se[w][lane + i * 32];
            bool qf = ord2f((unsigned int)(e >> 32)) <= thr;
            unsigned m = __ballot_sync(0xffffffffu, qf);
            if (qf) {
                int pos = nq + __popc(m & ((1u << lane) - 1u));
                sql[w][pos] = (int)(e & 0xFFFFFFFFu);
            }
            nq += __popc(m);
        }
        __syncwarp();
        unsigned long long best = ~0ull;
        const float* ccd = g_cc + (size_t)dep * K;
        for (int q = 0; q < nq; q++) {
            int cand = sql[w][q];
            const float4* cr = (const float4*)(cb + (size_t)cand * D);
            float4 c0 = cr[lane * 2], c1 = cr[lane * 2 + 1];
            float p = r0.x * c0.x + r0.y * c0.y + r0.z * c0.z + r0.w * c0.w
                    + r1.x * c1.x + r1.y * c1.y + r1.z * c1.z + r1.w * c1.w;
#pragma unroll
            for (int o = 16; o > 0; o >>= 1) p += __shfl_xor_sync(0xffffffffu, p, o);
            float dist = ccd[cand] - 2.f * p;
            unsigned long long key =
                ((unsigned long long)f2ord(dist) << 32) | (unsigned int)cand;
            if (key < best) best = key;
        }
        idx = (int)(best & 0xFFFFFFFFu);
    }

    const size_t o4 = (size_t)row * (D / 4) + lane * 2;
    const float4* cbv = (const float4*)(cb + (size_t)idx * D);
    float4 q0 = cbv[lane * 2], q1 = cbv[lane * 2 + 1];
    float4 a0 = ((const float4*)g_agg)[o4], a1 = ((const float4*)g_agg)[o4 + 1];
    a0.x += q0.x; a0.y += q0.y; a0.z += q0.z; a0.w += q0.w;
    a1.x += q1.x; a1.y += q1.y; a1.z += q1.z; a1.w += q1.w;
    float4 x0 = ((const float4*)x)[o4], x1 = ((const float4*)x)[o4 + 1];

    if (dep < DEPTH - 1) {
        float4 n0, n1;
        n0.x = r0.x - q0.x; n0.y = r0.y - q0.y; n0.z = r0.z - q0.z; n0.w = r0.w - q0.w;
        n1.x = r1.x - q1.x; n1.y = r1.y - q1.y; n1.z = r1.z - q1.z; n1.w = r1.w - q1.w;
        ((float4*)g_res)[o4] = n0;
        ((float4*)g_res)[o4 + 1] = n1;
        uint4 hh;
        hh.x = h2_as_u32(__float22half2_rn(make_float2(n0.x, n0.y)));
        hh.y = h2_as_u32(__float22half2_rn(make_float2(n0.z, n0.w)));
        hh.z = h2_as_u32(__float22half2_rn(make_float2(n1.x, n1.y)));
        hh.w = h2_as_u32(__float22half2_rn(make_float2(n1.z, n1.w)));
        *(uint4*)(g_res_h + (size_t)row * D + lane * 8) = hh;
        ((float4*)g_agg)[o4] = a0;
        ((float4*)g_agg)[o4 + 1] = a1;
    } else {
        float4 ov0, ov1;
        ov0.x = x0.x + (a0.x - x0.x); ov0.y = x0.y + (a0.y - x0.y);
        ov0.z = x0.z + (a0.z - x0.z); ov0.w = x0.w + (a0.w - x0.w);
        ov1.x = x1.x + (a1.x - x1.x); ov1.y = x1.y + (a1.y - x1.y);
        ov1.z = x1.z + (a1.z - x1.z); ov1.w = x1.w + (a1.w - x1.w);
        ((float4*)out)[o4] = ov0;
        ((float4*)out)[o4 + 1] = ov1;
    }

    float d0x = x0.x - a0.x, d0y = x0.y - a0.y, d0z = x0.z - a0.z, d0w = x0.w - a0.w;
    float d1x = x1.x - a1.x, d1y = x1.y - a1.y, d1z = x1.z - a1.z, d1w = x1.w - a1.w;
    float s2 = d0x * d0x + d0y * d0y + d0z * d0z + d0w * d0w
             + d1x * d1x + d1y * d1y + d1z * d1z + d1w * d1w;
#pragma unroll
    for (int o = 16; o > 0; o >>= 1) s2 += __shfl_down_sync(0xffffffffu, s2, o);
    if (lane == 0) {
        wloss[w] = s2;
        codes[(size_t)row * DEPTH + dep] = (float)idx;
    }
    __syncthreads();
    if (threadIdx.x == 0) {
        float t = 0.f;
#pragma unroll
        for (int i = 0; i < 8; i++) t += wloss[i];
        atomicAdd(loss, t * LOSS_SCALE);
    }
}

extern "C" void kernel_launch(void* const* d_in, const int* in_sizes, int n_in,
                              void* d_out, int out_size) {
    const float* x = (const float*)d_in[0];
    const float* cbs = (const float*)d_in[1];
    float* out = (float*)d_out;
    float* loss = out + (size_t)N_ROWS * D;
    float* codes = loss + 1;

    cudaFuncSetAttribute(k_gemm, cudaFuncAttributeMaxDynamicSharedMemorySize, SMEMT);

    k_init<<<(N_ROWS * D + 255) / 256, 256>>>(x);         // launch 0
    k_cb<<<DEPTH * K, 256>>>(cbs);                        // launch 1
    k_zero<<<1, 32>>>(loss);                              // launch 2

    for (int d = 0; d < DEPTH; d++) {
        const float* cb = cbs + (size_t)d * CB_STRIDE;
        dim3 grid(N_ROWS / BM, K / BN2);
        k_gemm<<<grid, 256, SMEMT>>>(d);                  // launches 3,5,7,9
        k_finish<<<N_ROWS / 8, 256>>>(x, cb, out, codes, loss, d);
    }
}

// round 12
// speedup vs baseline: 1.0480x; 1.0480x over previous
#include <cuda_runtime.h>
#include <cuda_fp16.h>
#include <cstdint>

#define N_ROWS 8192
#define D      256
#define K      8192
#define DEPTH  4
#define CB_STRIDE ((K + 1) * D)
#define LOSS_SCALE (0.25f / (4.0f * 2097152.0f))
#define MARGIN 8e-3f
#define FLT_BIG 3.402823466e38f

#define BM 128
#define TILE16 16384                 // 128 rows x 128B, pad-free (XOR swizzle)
#define SM_B  (4 * TILE16)           // A resident: 4 chunk tiles = 65536
#define NBSTG 3
#define SMEMT (SM_B + NBSTG * TILE16)   // 114688 -> 2 CTAs/SM

#define NJOBS 2048                   // 64 row-tiles x 32 cand-tiles (y-major)
#define NCTA  304                    // 152 SMs x 2
#define JBASE (NJOBS / NCTA)         // 6
#define JREM  (NJOBS - JBASE * NCTA) // 224

// ---------------- persistent scratch ----------------
__device__ __align__(256) float  g_res[N_ROWS * D];
__device__ __align__(256) float  g_agg[N_ROWS * D];
__device__ __align__(256) __half g_res_h[N_ROWS * D];
__device__ __align__(256) __half g_cb_h[DEPTH * K * D];
__device__ __align__(16)  float  g_cc[DEPTH * K];
__device__ __align__(16)  unsigned long long g_top[N_ROWS * 128];  // 32 tiles x 4

// ---------------- helpers ----------------
__device__ __forceinline__ uint32_t smem_u32(const void* p) {
    uint32_t a;
    asm("{ .reg .u64 t; cvta.to.shared.u64 t, %1; cvt.u32.u64 %0, t; }" : "=r"(a) : "l"(p));
    return a;
}
__device__ __forceinline__ uint32_t swz(uint32_t x) { return x ^ ((x >> 3) & 0x70u); }
__device__ __forceinline__ uint32_t h2_as_u32(__half2 h) {
    return *reinterpret_cast<uint32_t*>(&h);
}
__device__ __forceinline__ unsigned int f2ord(float f) {
    unsigned int u = __float_as_uint(f);
    return (u & 0x80000000u) ? ~u : (u | 0x80000000u);
}
__device__ __forceinline__ float ord2f(unsigned int o) {
    unsigned int u = (o & 0x80000000u) ? (o & 0x7FFFFFFFu) : ~o;
    return __uint_as_float(u);
}
__device__ __forceinline__ void merge2(unsigned long long& b1, unsigned long long& b2,
                                       unsigned long long o1, unsigned long long o2) {
    if (o1 < b1) { b2 = (b1 < o2) ? b1 : o2; b1 = o1; }
    else if (o1 < b2) { b2 = o1; }
}
__device__ __forceinline__ void push2(unsigned long long& b1, unsigned long long& b2,
                                      unsigned long long k) {
    if (k < b1) { b2 = b1; b1 = k; }
    else if (k < b2) { b2 = k; }
}

__device__ __forceinline__ void cpa16(uint32_t dst, const void* src) {
    asm volatile("cp.async.cg.shared.global [%0], [%1], 16;" :: "r"(dst), "l"(src));
}
#define CP_COMMIT() asm volatile("cp.async.commit_group;" ::: "memory")
#define CP_WAIT(n)  asm volatile("cp.async.wait_group %0;" :: "n"(n) : "memory")

#define LDSM4(r0, r1, r2, r3, a) \
    asm volatile("ldmatrix.sync.aligned.m8n8.x4.shared.b16 {%0,%1,%2,%3}, [%4];" \
                 : "=r"(r0), "=r"(r1), "=r"(r2), "=r"(r3) : "r"(a))

#define MMA16816(c, a, b0, b1) \
    asm volatile("mma.sync.aligned.m16n8k16.row.col.f32.f16.f16.f32 " \
                 "{%0,%1,%2,%3},{%4,%5,%6,%7},{%8,%9},{%0,%1,%2,%3};" \
                 : "+f"((c)[0]), "+f"((c)[1]), "+f"((c)[2]), "+f"((c)[3]) \
                 : "r"((a)[0]), "r"((a)[1]), "r"((a)[2]), "r"((a)[3]), "r"(b0), "r"(b1))

// reduce two values across a 256-thread block; result in thread 0
__device__ __forceinline__ void blockReduce2_256(float& a, float& b) {
    __shared__ float sa[8], sb2[8];
    int lane = threadIdx.x & 31, w = threadIdx.x >> 5;
#pragma unroll
    for (int o = 16; o > 0; o >>= 1) {
        a += __shfl_down_sync(0xffffffffu, a, o);
        b += __shfl_down_sync(0xffffffffu, b, o);
    }
    if (lane == 0) { sa[w] = a; sb2[w] = b; }
    __syncthreads();
    if (w == 0) {
        a = (lane < 8) ? sa[lane] : 0.f;
        b = (lane < 8) ? sb2[lane] : 0.f;
#pragma unroll
        for (int o = 4; o > 0; o >>= 1) {
            a += __shfl_down_sync(0xffu, a, o);
            b += __shfl_down_sync(0xffu, b, o);
        }
    }
}

// ---------------- setup ----------------
__global__ void k_init(const float* __restrict__ x) {
    int i = blockIdx.x * blockDim.x + threadIdx.x;
    if (i < N_ROWS * D) {
        float v = x[i];
        g_res[i] = v; g_agg[i] = 0.f;
        g_res_h[i] = __float2half_rn(v);
    }
}

__global__ void k_cb(const float* __restrict__ cbs) {
    int rid = blockIdx.x;                     // 0 .. DEPTH*K-1
    int dd = rid / K, r = rid % K;
    float v = cbs[(size_t)dd * CB_STRIDE + (size_t)r * D + threadIdx.x];
    g_cb_h[(size_t)rid * D + threadIdx.x] = __float2half_rn(v);
    float a = v * v, b = 0.f;
    blockReduce2_256(a, b);
    if (threadIdx.x == 0) g_cc[rid] = a;
}

__global__ void k_zero(float* __restrict__ loss) {
    if (threadIdx.x == 0) *loss = 0.f;
}

// fold one 128-col sub-tile's accumulators into running float top-2, zero acc
__device__ __forceinline__ void consume_acc(
        float acc[2][8][4], const float* __restrict__ cc, int colBase,
        float d1[4], float d2[4], int i1[4], int i2[4]) {
#pragma unroll
    for (int mb = 0; mb < 2; mb++) {
#pragma unroll
        for (int rb = 0; rb < 2; rb++) {
            const int s = mb * 2 + rb;
#pragma unroll
            for (int nf = 0; nf < 8; nf++) {
                int col = colBase + nf * 8;
                float2 c2 = *(const float2*)&cc[col];
                float k0 = fmaf(-2.f, acc[mb][nf][rb * 2 + 0], c2.x);
                float k1 = fmaf(-2.f, acc[mb][nf][rb * 2 + 1], c2.y);
                if (k0 < d2[s]) {
                    if (k0 < d1[s]) { d2[s] = d1[s]; i2[s] = i1[s]; d1[s] = k0; i1[s] = col; }
                    else { d2[s] = k0; i2[s] = col; }
                }
                if (k1 < d2[s]) {
                    if (k1 < d1[s]) { d2[s] = d1[s]; i2[s] = i1[s]; d1[s] = k1; i1[s] = col + 1; }
                    else { d2[s] = k1; i2[s] = col + 1; }
                }
                acc[mb][nf][rb * 2 + 0] = 0.f;
                acc[mb][nf][rb * 2 + 1] = 0.f;
            }
        }
    }
}

// ---------------- persistent HMMA GEMM + per-warp top-2 ----------------
// grid = 304 CTAs, block = 256 (8 warps: 4 row x 2 col, warp tile 32x64)
// Each CTA owns 6-7 consecutive y-major jobs (job = bx*32 + by ->
// 128 rows x 256 cands). A (128x256) stays resident across jobs with the
// same bx; B streams through 3 stages with the pipeline running
// continuously across job boundaries (stage = global-iter mod 3).
__global__ void __launch_bounds__(256, 2) k_gemm(int dep) {
    extern __shared__ char smem[];
    const uint32_t sb = smem_u32(smem);
    const int tid = threadIdx.x, lane = tid & 31, wid = tid >> 5;
    const int wm = wid & 3, wn = wid >> 2;

    const int r0 = tid >> 3, j0 = tid & 7;
    uint32_t sdst[4];
#pragma unroll
    for (int i = 0; i < 4; i++) sdst[i] = swz((uint32_t)(r0 + i * 32) * 128u + j0 * 16u);
    const uint32_t gA = (uint32_t)r0 * 512u + (uint32_t)j0 * 16u;

    const char* Bg0 = (const char*)(g_cb_h + (size_t)dep * K * D);
    const float* cc = g_cc + (size_t)dep * K;

    const int c = blockIdx.x;
    const int startJ = c * JBASE + (c < JREM ? c : JREM);
    const int cntJ = JBASE + (c < JREM ? 1 : 0);

    float acc[2][8][4];
#pragma unroll
    for (int a = 0; a < 2; a++)
#pragma unroll
        for (int b = 0; b < 8; b++)
#pragma unroll
            for (int q = 0; q < 4; q++) acc[a][b][q] = 0.f;

    float d1[4] = {FLT_BIG, FLT_BIG, FLT_BIG, FLT_BIG};
    float d2[4] = {FLT_BIG, FLT_BIG, FLT_BIG, FLT_BIG};
    int   i1[4] = {0, 0, 0, 0}, i2[4] = {0, 0, 0, 0};

    const uint32_t aLin0 = (uint32_t)((wm * 32 + (lane & 15)) * 128 + (lane >> 4) * 16);
    const uint32_t aLin1 = aLin0 + 16 * 128;
    const uint32_t bLin  = (uint32_t)((wn * 64 + (lane & 7) + ((lane >> 4) << 3)) * 128 +
                                      ((lane >> 3) & 1) * 16);

    int curBx = -1;
    int gi3 = 0;          // global iteration mod 3 (current B stage)
    int rowBase = 0;

    for (int jj = 0; jj < cntJ; jj++) {
        const int job = startJ + jj;
        const int bx = job >> 5, by = job & 31;
        const char* BgC = Bg0 + (size_t)(by * 256) * 512;
        const bool hasNext = (jj + 1 < cntJ);
        const char* BgN = Bg0 + (size_t)(((job + 1) & 31) * 256) * 512;

        bool fresh = false;
        if (bx != curBx) {
            __syncthreads();                      // all warps done reading old A
            rowBase = bx * BM;
            const char* Ag = (const char*)(g_res_h + (size_t)rowBase * D);
#pragma unroll
            for (int chA = 0; chA < 4; chA++)
#pragma unroll
                for (int i = 0; i < 4; i++)
                    cpa16(sb + chA * TILE16 + sdst[i],
                          Ag + gA + i * 32u * 512u + (uint32_t)chA * 128u);
            if (curBx < 0) {
                // very first job: B(0) -> stage 0 (same group as A), B(1) -> stage 1
#pragma unroll
                for (int i = 0; i < 4; i++)
                    cpa16(sb + SM_B + sdst[i], BgC + gA + i * 32u * 512u);
                CP_COMMIT();
#pragma unroll
                for (int i = 0; i < 4; i++)
                    cpa16(sb + SM_B + TILE16 + sdst[i], BgC + gA + i * 32u * 512u + 128u);
                CP_COMMIT();
            } else {
                CP_COMMIT();                      // A-only group (B(0),B(1) prefetched)
            }
            fresh = true;
            curBx = bx;
        }

#pragma unroll
        for (int it = 0; it < 8; it++) {
            if ((it == 0 && fresh) || (it == 7 && !hasNext)) { CP_WAIT(0); }
            else { CP_WAIT(1); }
            __syncthreads();

            // prefetch logical iteration it+2 into stage (gi3+2)%3
            {
                const uint32_t pstg = sb + SM_B +
                    (uint32_t)((gi3 + 2 >= 3) ? gi3 - 1 : gi3 + 2) * TILE16;
                const int t = it + 2;
                if (t < 8) {
                    const uint32_t bsrc = (uint32_t)(t >> 2) * 65536u + (uint32_t)(t & 3) * 128u;
#pragma unroll
                    for (int i = 0; i < 4; i++)
                        cpa16(pstg + sdst[i], BgC + gA + i * 32u * 512u + bsrc);
                    CP_COMMIT();
                } else if (hasNext) {
                    const int t2 = t - 8;
                    const uint32_t bsrc = (uint32_t)(t2 >> 2) * 65536u + (uint32_t)(t2 & 3) * 128u;
#pragma unroll
                    for (int i = 0; i < 4; i++)
                        cpa16(pstg + sdst[i], BgN + gA + i * 32u * 512u + bsrc);
                    CP_COMMIT();
                }
            }

            const uint32_t aT = sb + (uint32_t)(it & 3) * TILE16;
            const uint32_t bT = sb + SM_B + (uint32_t)gi3 * TILE16;
#pragma unroll
            for (int ks = 0; ks < 4; ks++) {
                uint32_t A0[4], A1[4], Bf[4][4];
                LDSM4(A0[0], A0[1], A0[2], A0[3], aT + swz(aLin0 + ks * 32));
                LDSM4(A1[0], A1[1], A1[2], A1[3], aT + swz(aLin1 + ks * 32));
#pragma unroll
                for (int nb = 0; nb < 4; nb++)
                    LDSM4(Bf[nb][0], Bf[nb][1], Bf[nb][2], Bf[nb][3],
                          bT + swz(bLin + nb * 16 * 128 + ks * 32));
#pragma unroll
                for (int nb = 0; nb < 4; nb++) {
                    MMA16816(acc[0][nb * 2 + 0], A0, Bf[nb][0], Bf[nb][1]);
                    MMA16816(acc[0][nb * 2 + 1], A0, Bf[nb][2], Bf[nb][3]);
                    MMA16816(acc[1][nb * 2 + 0], A1, Bf[nb][0], Bf[nb][1]);
                    MMA16816(acc[1][nb * 2 + 1], A1, Bf[nb][2], Bf[nb][3]);
                }
            }

            if ((it & 3) == 3)
                consume_acc(acc, cc,
                            by * 256 + (it >> 2) * 128 + wn * 64 + (lane & 3) * 2,
                            d1, d2, i1, i2);

            gi3 = (gi3 + 1 == 3) ? 0 : gi3 + 1;
        }

        // per-job epilogue: warp-level merge + direct global store (no barriers)
#pragma unroll
        for (int s = 0; s < 4; s++) {
            unsigned long long b1 =
                ((unsigned long long)f2ord(d1[s]) << 32) | (unsigned int)i1[s];
            unsigned long long b2 =
                ((unsigned long long)f2ord(d2[s]) << 32) | (unsigned int)i2[s];
#pragma unroll
            for (int off = 1; off <= 2; off <<= 1) {
                unsigned long long o1 = __shfl_xor_sync(0xffffffffu, b1, off);
                unsigned long long o2 = __shfl_xor_sync(0xffffffffu, b2, off);
                merge2(b1, b2, o1, o2);
            }
            if ((lane & 3) == 0) {
                int rl = rowBase + wm * 32 + (s >> 1) * 16 + (s & 1) * 8 + (lane >> 2);
                size_t go = (size_t)rl * 128 + by * 4 + wn * 2;
                g_top[go + 0] = b1;
                g_top[go + 1] = b2;
            }
            d1[s] = FLT_BIG; d2[s] = FLT_BIG; i1[s] = 0; i2[s] = 0;
        }
    }
}

// ---------------- fused select + rescore + update: warp per row ----------------
// grid = N_ROWS/8 = 1024, block = 256 (8 warps)
__global__ void __launch_bounds__(256) k_finish(
        const float* __restrict__ x, const float* __restrict__ cb,
        float* __restrict__ out, float* __restrict__ codes,
        float* __restrict__ loss, int dep) {
    const int w = threadIdx.x >> 5, lane = threadIdx.x & 31;
    const int row = blockIdx.x * 8 + w;
    __shared__ unsigned long long se[8][128];
    __shared__ int sql[8][128];
    __shared__ float wloss[8];

    const unsigned long long* gt = g_top + (size_t)row * 128;
    unsigned long long b1 = ~0ull, b2 = ~0ull;
#pragma unroll
    for (int i = 0; i < 4; i++) {
        unsigned long long e = gt[lane + i * 32];
        se[w][lane + i * 32] = e;
        push2(b1, b2, e);
    }
#pragma unroll
    for (int off = 16; off > 0; off >>= 1) {
        unsigned long long o1 = __shfl_xor_sync(0xffffffffu, b1, off);
        unsigned long long o2 = __shfl_xor_sync(0xffffffffu, b2, off);
        merge2(b1, b2, o1, o2);
    }
    float d1 = ord2f((unsigned int)(b1 >> 32));
    float d2 = ord2f((unsigned int)(b2 >> 32));
    int idx = (int)(b1 & 0xFFFFFFFFu);

    const float4* rr = (const float4*)(g_res + (size_t)row * D);
    float4 r0 = rr[lane * 2], r1 = rr[lane * 2 + 1];

    if (d2 - d1 < MARGIN) {
        const float thr = d1 + MARGIN;
        int nq = 0;
        __syncwarp();
#pragma unroll
        for (int i = 0; i < 4; i++) {
            unsigned long long e = se[w][lane + i * 32];
            bool qf = ord2f((unsigned int)(e >> 32)) <= thr;
            unsigned m = __ballot_sync(0xffffffffu, qf);
            if (qf) {
                int pos = nq + __popc(m & ((1u << lane) - 1u));
                sql[w][pos] = (int)(e & 0xFFFFFFFFu);
            }
            nq += __popc(m);
        }
        __syncwarp();
        unsigned long long best = ~0ull;
        const float* ccd = g_cc + (size_t)dep * K;
        for (int q = 0; q < nq; q++) {
            int cand = sql[w][q];
            const float4* cr = (const float4*)(cb + (size_t)cand * D);
            float4 c0 = cr[lane * 2], c1 = cr[lane * 2 + 1];
            float p = r0.x * c0.x + r0.y * c0.y + r0.z * c0.z + r0.w * c0.w
                    + r1.x * c1.x + r1.y * c1.y + r1.z * c1.z + r1.w * c1.w;
#pragma unroll
            for (int o = 16; o > 0; o >>= 1) p += __shfl_xor_sync(0xffffffffu, p, o);
            float dist = ccd[cand] - 2.f * p;
            unsigned long long key =
                ((unsigned long long)f2ord(dist) << 32) | (unsigned int)cand;
            if (key < best) best = key;
        }
        idx = (int)(best & 0xFFFFFFFFu);
    }

    const size_t o4 = (size_t)row * (D / 4) + lane * 2;
    const float4* cbv = (const float4*)(cb + (size_t)idx * D);
    float4 q0 = cbv[lane * 2], q1 = cbv[lane * 2 + 1];
    float4 a0 = ((const float4*)g_agg)[o4], a1 = ((const float4*)g_agg)[o4 + 1];
    a0.x += q0.x; a0.y += q0.y; a0.z += q0.z; a0.w += q0.w;
    a1.x += q1.x; a1.y += q1.y; a1.z += q1.z; a1.w += q1.w;
    float4 x0 = ((const float4*)x)[o4], x1 = ((const float4*)x)[o4 + 1];

    if (dep < DEPTH - 1) {
        float4 n0, n1;
        n0.x = r0.x - q0.x; n0.y = r0.y - q0.y; n0.z = r0.z - q0.z; n0.w = r0.w - q0.w;
        n1.x = r1.x - q1.x; n1.y = r1.y - q1.y; n1.z = r1.z - q1.z; n1.w = r1.w - q1.w;
        ((float4*)g_res)[o4] = n0;
        ((float4*)g_res)[o4 + 1] = n1;
        uint4 hh;
        hh.x = h2_as_u32(__float22half2_rn(make_float2(n0.x, n0.y)));
        hh.y = h2_as_u32(__float22half2_rn(make_float2(n0.z, n0.w)));
        hh.z = h2_as_u32(__float22half2_rn(make_float2(n1.x, n1.y)));
        hh.w = h2_as_u32(__float22half2_rn(make_float2(n1.z, n1.w)));
        *(uint4*)(g_res_h + (size_t)row * D + lane * 8) = hh;
        ((float4*)g_agg)[o4] = a0;
        ((float4*)g_agg)[o4 + 1] = a1;
    } else {
        float4 ov0, ov1;
        ov0.x = x0.x + (a0.x - x0.x); ov0.y = x0.y + (a0.y - x0.y);
        ov0.z = x0.z + (a0.z - x0.z); ov0.w = x0.w + (a0.w - x0.w);
        ov1.x = x1.x + (a1.x - x1.x); ov1.y = x1.y + (a1.y - x1.y);
        ov1.z = x1.z + (a1.z - x1.z); ov1.w = x1.w + (a1.w - x1.w);
        ((float4*)out)[o4] = ov0;
        ((float4*)out)[o4 + 1] = ov1;
    }

    float d0x = x0.x - a0.x, d0y = x0.y - a0.y, d0z = x0.z - a0.z, d0w = x0.w - a0.w;
    float d1x = x1.x - a1.x, d1y = x1.y - a1.y, d1z = x1.z - a1.z, d1w = x1.w - a1.w;
    float s2 = d0x * d0x + d0y * d0y + d0z * d0z + d0w * d0w
             + d1x * d1x + d1y * d1y + d1z * d1z + d1w * d1w;
#pragma unroll
    for (int o = 16; o > 0; o >>= 1) s2 += __shfl_down_sync(0xffffffffu, s2, o);
    if (lane == 0) {
        wloss[w] = s2;
        codes[(size_t)row * DEPTH + dep] = (float)idx;
    }
    __syncthreads();
    if (threadIdx.x == 0) {
        float t = 0.f;
#pragma unroll
        for (int i = 0; i < 8; i++) t += wloss[i];
        atomicAdd(loss, t * LOSS_SCALE);
    }
}

extern "C" void kernel_launch(void* const* d_in, const int* in_sizes, int n_in,
                              void* d_out, int out_size) {
    const float* x = (const float*)d_in[0];
    const float* cbs = (const float*)d_in[1];
    float* out = (float*)d_out;
    float* loss = out + (size_t)N_ROWS * D;
    float* codes = loss + 1;

    cudaFuncSetAttribute(k_gemm, cudaFuncAttributeMaxDynamicSharedMemorySize, SMEMT);

    k_init<<<(N_ROWS * D + 255) / 256, 256>>>(x);         // launch 0
    k_cb<<<DEPTH * K, 256>>>(cbs);                        // launch 1
    k_zero<<<1, 32>>>(loss);                              // launch 2

    for (int d = 0; d < DEPTH; d++) {
        const float* cb = cbs + (size_t)d * CB_STRIDE;
        k_gemm<<<NCTA, 256, SMEMT>>>(d);                  // launches 3,5,7,9
        k_finish<<<N_ROWS / 8, 256>>>(x, cb, out, codes, loss, d);
    }
}